// round 2
// baseline (speedup 1.0000x reference)
#include <cuda_runtime.h>
#include <cuda_bf16.h>
#include <math.h>

// Problem constants
#define B_   8
#define S_   1024
#define D_   512
#define H_   8
#define DK_  64
#define WIDTH_ 8
#define S2_  1040          // S + 2*WIDTH
#define NHW_ 2
#define MROWS_FULL (B_ * S2_)   // 8320
#define MROWS_MID  (B_ * S_)    // 8192

// ------------------------------------------------------------------
// Scratch (static device globals; no allocation allowed)
// ------------------------------------------------------------------
__device__ float g_newin[MROWS_FULL * D_];   // padded input (B,S2,D)
__device__ float g_q[MROWS_FULL * D_];
__device__ float g_k[MROWS_FULL * D_];
__device__ float g_v[MROWS_FULL * D_];
__device__ float g_attn[MROWS_MID * D_];     // attention out, middle rows only
__device__ float g_cur[MROWS_MID * D_];      // highway state
__device__ float g_proj[MROWS_MID * 2 * D_]; // highway projection (8192 x 1024)

// ------------------------------------------------------------------
// Build new_in = concat(left_pad, x, right_pad) along seq dim
// ------------------------------------------------------------------
__global__ void build_newin_kernel(const float* __restrict__ x,
                                   const float* __restrict__ lpad,
                                   const float* __restrict__ rpad,
                                   float* __restrict__ dst) {
    int idx = blockIdx.x * blockDim.x + threadIdx.x;   // over float4s
    int total = MROWS_FULL * (D_ / 4);
    if (idx >= total) return;
    int d4  = idx % (D_ / 4);
    int row = idx / (D_ / 4);
    int t = row % S2_;
    int b = row / S2_;
    float4 v;
    if (t < WIDTH_) {
        v = ((const float4*)lpad)[t * (D_ / 4) + d4];
    } else if (t < WIDTH_ + S_) {
        v = ((const float4*)x)[((size_t)b * S_ + (t - WIDTH_)) * (D_ / 4) + d4];
    } else {
        v = ((const float4*)rpad)[(t - WIDTH_ - S_) * (D_ / 4) + d4];
    }
    ((float4*)dst)[(size_t)row * (D_ / 4) + d4] = v;
}

// ------------------------------------------------------------------
// SGEMM: C[M,N] = A[M,K] @ B[K,N] + bias[N]
// BM=BN=128, BK=16, TM=TN=8, 256 threads, double-buffered smem with
// register-staged prefetch. Requires M%128==0, N%128==0, K%16==0.
// ------------------------------------------------------------------
#define BM 128
#define BN 128
#define BK 16
#define TM 8
#define TN 8
#define BMP 132   // padded A-smem row to break store bank conflicts

__global__ __launch_bounds__(256)
void sgemm_bias_kernel(const float* __restrict__ A,
                       const float* __restrict__ Bm,
                       const float* __restrict__ bias,
                       float* __restrict__ C,
                       int M, int N, int K) {
    __shared__ float As[2][BK][BMP];
    __shared__ float Bs[2][BK][BN];

    int tid = threadIdx.x;
    int bm = blockIdx.y, bn = blockIdx.x;
    int tx = tid % 16;       // 16 thread-cols
    int ty = tid / 16;       // 16 thread-rows

    float acc[TM][TN];
#pragma unroll
    for (int i = 0; i < TM; i++)
#pragma unroll
        for (int j = 0; j < TN; j++) acc[i][j] = 0.f;

    // A-tile load mapping: 128 rows x 16 cols, one float4 per thread per pass, 2 passes
    int a_row = tid / 4;            // 0..63 (+64 second pass)
    int a_col = (tid % 4) * 4;      // 0,4,8,12
    // B-tile load mapping: 16 rows x 128 cols, one float4 per thread per pass, 2 passes
    int b_row = tid / 32;           // 0..7 (+8 second pass)
    int b_col = (tid % 32) * 4;     // 0..124

    const float* Aptr = A + (size_t)bm * BM * K;
    const float* Bptr = Bm + (size_t)bn * BN;

    float4 pa0, pa1, pb0, pb1;

    // ---- preload tile 0 into buffer 0 ----
    pa0 = *(const float4*)(Aptr + (size_t)a_row * K + a_col);
    pa1 = *(const float4*)(Aptr + (size_t)(a_row + 64) * K + a_col);
    pb0 = *(const float4*)(Bptr + (size_t)b_row * N + b_col);
    pb1 = *(const float4*)(Bptr + (size_t)(b_row + 8) * N + b_col);

    As[0][a_col + 0][a_row] = pa0.x;
    As[0][a_col + 1][a_row] = pa0.y;
    As[0][a_col + 2][a_row] = pa0.z;
    As[0][a_col + 3][a_row] = pa0.w;
    As[0][a_col + 0][a_row + 64] = pa1.x;
    As[0][a_col + 1][a_row + 64] = pa1.y;
    As[0][a_col + 2][a_row + 64] = pa1.z;
    As[0][a_col + 3][a_row + 64] = pa1.w;
    *(float4*)&Bs[0][b_row][b_col]     = pb0;
    *(float4*)&Bs[0][b_row + 8][b_col] = pb1;
    __syncthreads();

    int buf = 0;
    for (int k0 = BK; k0 < K + BK; k0 += BK) {
        bool has_next = (k0 < K);
        if (has_next) {
            // prefetch next tile into registers (overlaps with compute below)
            pa0 = *(const float4*)(Aptr + (size_t)a_row * K + k0 + a_col);
            pa1 = *(const float4*)(Aptr + (size_t)(a_row + 64) * K + k0 + a_col);
            pb0 = *(const float4*)(Bptr + (size_t)(k0 + b_row) * N + b_col);
            pb1 = *(const float4*)(Bptr + (size_t)(k0 + b_row + 8) * N + b_col);
        }

        // compute on current buffer
#pragma unroll
        for (int kk = 0; kk < BK; kk++) {
            float a[TM], b[TN];
#pragma unroll
            for (int i = 0; i < TM; i += 4)
                *(float4*)&a[i] = *(const float4*)&As[buf][kk][ty * TM + i];
#pragma unroll
            for (int j = 0; j < TN; j += 4)
                *(float4*)&b[j] = *(const float4*)&Bs[buf][kk][tx * TN + j];
#pragma unroll
            for (int i = 0; i < TM; i++)
#pragma unroll
                for (int j = 0; j < TN; j++)
                    acc[i][j] += a[i] * b[j];
        }

        if (has_next) {
            int nb = buf ^ 1;
            As[nb][a_col + 0][a_row] = pa0.x;
            As[nb][a_col + 1][a_row] = pa0.y;
            As[nb][a_col + 2][a_row] = pa0.z;
            As[nb][a_col + 3][a_row] = pa0.w;
            As[nb][a_col + 0][a_row + 64] = pa1.x;
            As[nb][a_col + 1][a_row + 64] = pa1.y;
            As[nb][a_col + 2][a_row + 64] = pa1.z;
            As[nb][a_col + 3][a_row + 64] = pa1.w;
            *(float4*)&Bs[nb][b_row][b_col]     = pb0;
            *(float4*)&Bs[nb][b_row + 8][b_col] = pb1;
            __syncthreads();
            buf = nb;
        }
    }

#pragma unroll
    for (int i = 0; i < TM; i++) {
        int row = bm * BM + ty * TM + i;
#pragma unroll
        for (int j = 0; j < TN; j += 4) {
            int col = bn * BN + tx * TN + j;
            float4 bs = *(const float4*)(bias + col);
            float4 o;
            o.x = acc[i][j + 0] + bs.x;
            o.y = acc[i][j + 1] + bs.y;
            o.z = acc[i][j + 2] + bs.z;
            o.w = acc[i][j + 3] + bs.w;
            *(float4*)(C + (size_t)row * N + col) = o;
        }
    }
}

// ------------------------------------------------------------------
// Banded attention: one warp per (b, i_local, h).
// dir=0 (left):  keys j in [max(0,i-9), i]
// dir=1 (right): keys j in [i, min(S2-1, i+9)]
// Writes compact output rows (b*S + i_local).
// ------------------------------------------------------------------
__global__ void banded_attn_kernel(const float* __restrict__ Q,
                                   const float* __restrict__ K,
                                   const float* __restrict__ V,
                                   float* __restrict__ O,
                                   int dir) {
    int warp_g = (blockIdx.x * blockDim.x + threadIdx.x) >> 5;
    int lane = threadIdx.x & 31;
    if (warp_g >= B_ * S_ * H_) return;
    int h = warp_g % H_;
    int rem = warp_g / H_;
    int i_local = rem % S_;
    int b = rem / S_;
    int i = i_local + WIDTH_;                 // row in S2 space

    int j0, j1;
    if (dir == 0) { j0 = i - (WIDTH_ + 1); if (j0 < 0) j0 = 0; j1 = i; }
    else          { j0 = i; j1 = i + (WIDTH_ + 1); if (j1 > S2_ - 1) j1 = S2_ - 1; }
    int nj = j1 - j0 + 1;                     // <= 10

    int dcol = h * DK_ + lane * 2;
    const float2 qv = *(const float2*)(Q + ((size_t)(b * S2_ + i)) * D_ + dcol);

    float sc[WIDTH_ + 2];
    for (int t = 0; t < nj; t++) {
        int j = j0 + t;
        float2 kv = *(const float2*)(K + ((size_t)(b * S2_ + j)) * D_ + dcol);
        float p = qv.x * kv.x + qv.y * kv.y;
#pragma unroll
        for (int off = 16; off > 0; off >>= 1)
            p += __shfl_xor_sync(0xffffffffu, p, off);
        sc[t] = p * 0.125f;   // 1/sqrt(64)
    }
    // softmax over nj scores (identical in all lanes)
    float m = sc[0];
    for (int t = 1; t < nj; t++) m = fmaxf(m, sc[t]);
    float ssum = 0.f;
    for (int t = 0; t < nj; t++) { sc[t] = __expf(sc[t] - m); ssum += sc[t]; }
    float inv = 1.0f / ssum;

    float2 o = make_float2(0.f, 0.f);
    for (int t = 0; t < nj; t++) {
        int j = j0 + t;
        float2 vv = *(const float2*)(V + ((size_t)(b * S2_ + j)) * D_ + dcol);
        float w = sc[t] * inv;
        o.x += w * vv.x;
        o.y += w * vv.y;
    }
    *(float2*)(O + ((size_t)(b * S_ + i_local)) * D_ + dcol) = o;
}

// ------------------------------------------------------------------
// Relative-position add: cur[b,s,:] += sum_{j=0..WIDTH} w[j]*new_in[b, s+off+j, :]
// ------------------------------------------------------------------
__global__ void rel_add_kernel(float* __restrict__ cur,
                               const float* __restrict__ newin,
                               const float* __restrict__ w,
                               int off) {
    int idx = blockIdx.x * blockDim.x + threadIdx.x;   // over float4
    int total = MROWS_MID * (D_ / 4);
    if (idx >= total) return;
    int d4 = idx % (D_ / 4);
    int row = idx / (D_ / 4);
    int s = row % S_;
    int b = row / S_;

    float4 acc = ((float4*)cur)[(size_t)row * (D_ / 4) + d4];
#pragma unroll
    for (int j = 0; j <= WIDTH_; j++) {
        float wj = w[j];
        float4 v = ((const float4*)newin)[((size_t)(b * S2_ + s + off + j)) * (D_ / 4) + d4];
        acc.x += wj * v.x; acc.y += wj * v.y; acc.z += wj * v.z; acc.w += wj * v.w;
    }
    ((float4*)cur)[(size_t)row * (D_ / 4) + d4] = acc;
}

// ------------------------------------------------------------------
// Highway combine: new = g*cur + (1-g)*relu(nl)
// proj is (rows x 2D): [:, :D] = nl pre-act, [:, D:] = gate pre-act.
// ------------------------------------------------------------------
__global__ void highway_combine_kernel(const float* __restrict__ proj,
                                       const float* __restrict__ cur,
                                       float* __restrict__ outp,
                                       int out_stride, int col_off) {
    int idx = blockIdx.x * blockDim.x + threadIdx.x;   // over float4
    int total = MROWS_MID * (D_ / 4);
    if (idx >= total) return;
    int d4 = idx % (D_ / 4);
    int row = idx / (D_ / 4);

    float4 nl = ((const float4*)proj)[(size_t)row * (2 * D_ / 4) + d4];
    float4 gp = ((const float4*)proj)[(size_t)row * (2 * D_ / 4) + (D_ / 4) + d4];
    float4 xc = ((const float4*)cur)[(size_t)row * (D_ / 4) + d4];

    float4 o;
    {
        float g = 1.0f / (1.0f + __expf(-gp.x));
        o.x = g * xc.x + (1.0f - g) * fmaxf(nl.x, 0.f);
    }
    {
        float g = 1.0f / (1.0f + __expf(-gp.y));
        o.y = g * xc.y + (1.0f - g) * fmaxf(nl.y, 0.f);
    }
    {
        float g = 1.0f / (1.0f + __expf(-gp.z));
        o.z = g * xc.z + (1.0f - g) * fmaxf(nl.z, 0.f);
    }
    {
        float g = 1.0f / (1.0f + __expf(-gp.w));
        o.w = g * xc.w + (1.0f - g) * fmaxf(nl.w, 0.f);
    }
    *(float4*)(outp + (size_t)row * out_stride + col_off + d4 * 4) = o;
}

// ------------------------------------------------------------------
// Host orchestration
// ------------------------------------------------------------------
extern "C" void kernel_launch(void* const* d_in, const int* in_sizes, int n_in,
                              void* d_out, int out_size) {
    const float* x       = (const float*)d_in[0];
    const float* lattnW  = (const float*)d_in[1];
    const float* lattnB  = (const float*)d_in[2];
    const float* rattnW  = (const float*)d_in[3];
    const float* rattnB  = (const float*)d_in[4];
    const float* lpad    = (const float*)d_in[5];
    const float* rpad    = (const float*)d_in[6];
    const float* leftw   = (const float*)d_in[7];
    const float* rightw  = (const float*)d_in[8];
    const float* lhwW    = (const float*)d_in[9];
    const float* lhwB    = (const float*)d_in[10];
    const float* rhwW    = (const float*)d_in[11];
    const float* rhwB    = (const float*)d_in[12];
    float* out = (float*)d_out;

    float *newin, *q, *k, *v, *attn, *cur, *proj;
    cudaGetSymbolAddress((void**)&newin, g_newin);
    cudaGetSymbolAddress((void**)&q,     g_q);
    cudaGetSymbolAddress((void**)&k,     g_k);
    cudaGetSymbolAddress((void**)&v,     g_v);
    cudaGetSymbolAddress((void**)&attn,  g_attn);
    cudaGetSymbolAddress((void**)&cur,   g_cur);
    cudaGetSymbolAddress((void**)&proj,  g_proj);

    // 1. build padded input
    {
        int total = MROWS_FULL * (D_ / 4);
        build_newin_kernel<<<(total + 255) / 256, 256>>>(x, lpad, rpad, newin);
    }

    for (int side = 0; side < 2; side++) {
        const float* W   = side ? rattnW : lattnW;
        const float* bb  = side ? rattnB : lattnB;
        const float* hwW = side ? rhwW : lhwW;
        const float* hwB = side ? rhwB : lhwB;
        const float* rw  = side ? rightw : leftw;
        int rel_off = side ? WIDTH_ : 0;

        dim3 gFull(D_ / BN, MROWS_FULL / BM);   // 4 x 65
        dim3 gMid (D_ / BN, MROWS_MID  / BM);   // 4 x 64
        dim3 gHW  (2 * D_ / BN, MROWS_MID / BM);// 8 x 64

        // QKV projections over all S2 rows
        sgemm_bias_kernel<<<gFull, 256>>>(newin, W + 0 * D_ * D_, bb + 0 * D_, q, MROWS_FULL, D_, D_);
        sgemm_bias_kernel<<<gFull, 256>>>(newin, W + 1 * D_ * D_, bb + 1 * D_, k, MROWS_FULL, D_, D_);
        sgemm_bias_kernel<<<gFull, 256>>>(newin, W + 2 * D_ * D_, bb + 2 * D_, v, MROWS_FULL, D_, D_);

        // banded attention (middle rows only)
        {
            int warps = B_ * S_ * H_;              // 65536
            int threads = 256;                     // 8 warps / block
            int blocks = (warps * 32 + threads - 1) / threads;
            banded_attn_kernel<<<blocks, threads>>>(q, k, v, attn, side);
        }

        // output projection -> cur
        sgemm_bias_kernel<<<gMid, 256>>>(attn, W + 3 * D_ * D_, bb + 3 * D_, cur, MROWS_MID, D_, D_);

        // add relative-position term
        {
            int total = MROWS_MID * (D_ / 4);
            rel_add_kernel<<<(total + 255) / 256, 256>>>(cur, newin, rw, rel_off);
        }

        // highway layers
        for (int l = 0; l < NHW_; l++) {
            sgemm_bias_kernel<<<gHW, 256>>>(cur, hwW + (size_t)l * D_ * 2 * D_,
                                            hwB + (size_t)l * 2 * D_, proj,
                                            MROWS_MID, 2 * D_, D_);
            int total = MROWS_MID * (D_ / 4);
            if (l == NHW_ - 1) {
                highway_combine_kernel<<<(total + 255) / 256, 256>>>(
                    proj, cur, out, 2 * D_, side * D_);
            } else {
                highway_combine_kernel<<<(total + 255) / 256, 256>>>(
                    proj, cur, cur, D_, 0);
            }
        }
    }
}

// round 6
// speedup vs baseline: 2.2909x; 2.2909x over previous
#include <cuda_runtime.h>
#include <cuda_bf16.h>
#include <math.h>

// Problem constants
#define B_   8
#define S_   1024
#define D_   512
#define H_   8
#define DK_  64
#define WIDTH_ 8
#define S2_  1040          // S + 2*WIDTH
#define NHW_ 2
#define MROWS_FULL (B_ * S2_)   // 8320
#define MROWS_MID  (B_ * S_)    // 8192

// ------------------------------------------------------------------
// Scratch (static device globals; no allocation allowed)
// ------------------------------------------------------------------
__device__ float g_newin[MROWS_FULL * D_];        // padded input (B,S2,D)
__device__ float g_qkv[3 * MROWS_FULL * D_];      // q | k | v
__device__ float g_attn[MROWS_MID * D_];          // attention out, middle rows only
__device__ float g_cur[MROWS_MID * D_];           // highway state
__device__ float g_proj[MROWS_MID * 2 * D_];      // highway projection (8192 x 1024)

// ------------------------------------------------------------------
// tf32 helper
// ------------------------------------------------------------------
__device__ __forceinline__ float cvt_tf32(float x) {
    unsigned u;
    asm("cvt.rna.tf32.f32 %0, %1;" : "=r"(u) : "f"(x));
    return __uint_as_float(u);
}

// ------------------------------------------------------------------
// Build new_in = concat(left_pad, x, right_pad) along seq dim
// ------------------------------------------------------------------
__global__ void build_newin_kernel(const float* __restrict__ x,
                                   const float* __restrict__ lpad,
                                   const float* __restrict__ rpad,
                                   float* __restrict__ dst) {
    int idx = blockIdx.x * blockDim.x + threadIdx.x;   // over float4s
    int total = MROWS_FULL * (D_ / 4);
    if (idx >= total) return;
    int d4  = idx % (D_ / 4);
    int row = idx / (D_ / 4);
    int t = row % S2_;
    int b = row / S2_;
    float4 v;
    if (t < WIDTH_) {
        v = ((const float4*)lpad)[t * (D_ / 4) + d4];
    } else if (t < WIDTH_ + S_) {
        v = ((const float4*)x)[((size_t)b * S_ + (t - WIDTH_)) * (D_ / 4) + d4];
    } else {
        v = ((const float4*)rpad)[(t - WIDTH_ - S_) * (D_ / 4) + d4];
    }
    ((float4*)dst)[(size_t)row * (D_ / 4) + d4] = v;
}

// ------------------------------------------------------------------
// TF32 tensor-core GEMM: C[M,N] = A[M,K] @ W[K,N] + bias[N]
// BM=BN=128, BK=16, 256 threads = 8 warps (4x2), warp tile 32x64,
// mma.sync.m16n8k8.tf32, double-buffered smem with register prefetch.
// gridDim.z batches independent weight/bias/output (QKV fusion).
// Requires M%128==0, N%128==0, K%16==0.
// ------------------------------------------------------------------
#define BM 128
#define BN 128
#define BK 16
#define BKP 20   // padded k-stride (floats) -> conflict-free fragment LDS

__global__ __launch_bounds__(256, 2)
void tf32_gemm_bias(const float* __restrict__ A,
                    const float* __restrict__ W,
                    const float* __restrict__ bias,
                    float* __restrict__ C,
                    int M, int N, int K,
                    long strideW, int strideBias, long strideC) {
    __shared__ float As[2][BM][BKP];   // [m][k]
    __shared__ float Bs[2][BN][BKP];   // [n][k] (transposed)

    const float* Wz = W + (size_t)blockIdx.z * strideW;
    const float* bz = bias + (size_t)blockIdx.z * strideBias;
    float* Cz = C + (size_t)blockIdx.z * strideC;

    int tid  = threadIdx.x;
    int lane = tid & 31;
    int wid  = tid >> 5;
    int warp_m = wid & 3;     // 4 warps along M (32 rows each)
    int warp_n = wid >> 2;    // 2 warps along N (64 cols each)
    int gid = lane >> 2;      // 0..7
    int tig = lane & 3;       // 0..3

    int bm = blockIdx.y, bn = blockIdx.x;

    // A loader: 128 rows x 16 cols, float4 per thread, rows tid/4 and +64
    int a_row = tid >> 2;            // 0..63
    int a_col = (tid & 3) << 2;      // 0,4,8,12
    // B loader: 16 rows x 128 cols; thread owns one col, 8 consecutive k-rows
    int b_col = tid & 127;
    int b_r8  = (tid >> 7) << 3;     // 0 or 8

    const float* Aptr = A + (size_t)bm * BM * K;
    const float* Bptr = Wz + bn * BN;

    float acc[2][8][4];
#pragma unroll
    for (int i = 0; i < 2; i++)
#pragma unroll
        for (int j = 0; j < 8; j++)
#pragma unroll
            for (int t = 0; t < 4; t++) acc[i][j][t] = 0.f;

    float4 ra0, ra1;
    float rb[8];

    // ---- preload tile 0 ----
    ra0 = *(const float4*)(Aptr + (size_t)a_row * K + a_col);
    ra1 = *(const float4*)(Aptr + (size_t)(a_row + 64) * K + a_col);
#pragma unroll
    for (int r = 0; r < 8; r++)
        rb[r] = Bptr[(size_t)(b_r8 + r) * N + b_col];

    *(float4*)&As[0][a_row][a_col] =
        make_float4(cvt_tf32(ra0.x), cvt_tf32(ra0.y), cvt_tf32(ra0.z), cvt_tf32(ra0.w));
    *(float4*)&As[0][a_row + 64][a_col] =
        make_float4(cvt_tf32(ra1.x), cvt_tf32(ra1.y), cvt_tf32(ra1.z), cvt_tf32(ra1.w));
    *(float4*)&Bs[0][b_col][b_r8] =
        make_float4(cvt_tf32(rb[0]), cvt_tf32(rb[1]), cvt_tf32(rb[2]), cvt_tf32(rb[3]));
    *(float4*)&Bs[0][b_col][b_r8 + 4] =
        make_float4(cvt_tf32(rb[4]), cvt_tf32(rb[5]), cvt_tf32(rb[6]), cvt_tf32(rb[7]));
    __syncthreads();

    int buf = 0;
    for (int k0 = BK; k0 < K + BK; k0 += BK) {
        bool has_next = (k0 < K);
        if (has_next) {
            ra0 = *(const float4*)(Aptr + (size_t)a_row * K + k0 + a_col);
            ra1 = *(const float4*)(Aptr + (size_t)(a_row + 64) * K + k0 + a_col);
#pragma unroll
            for (int r = 0; r < 8; r++)
                rb[r] = Bptr[(size_t)(k0 + b_r8 + r) * N + b_col];
        }

        // compute on current buffer: 2 k-steps of k8
#pragma unroll
        for (int kk = 0; kk < 2; kk++) {
            int kc = kk * 8 + tig;
            unsigned af[2][4];
#pragma unroll
            for (int tm = 0; tm < 2; tm++) {
                int r = warp_m * 32 + tm * 16 + gid;
                af[tm][0] = __float_as_uint(As[buf][r][kc]);
                af[tm][1] = __float_as_uint(As[buf][r + 8][kc]);
                af[tm][2] = __float_as_uint(As[buf][r][kc + 4]);
                af[tm][3] = __float_as_uint(As[buf][r + 8][kc + 4]);
            }
            unsigned bf[8][2];
#pragma unroll
            for (int tn = 0; tn < 8; tn++) {
                int c = warp_n * 64 + tn * 8 + gid;
                bf[tn][0] = __float_as_uint(Bs[buf][c][kc]);
                bf[tn][1] = __float_as_uint(Bs[buf][c][kc + 4]);
            }
#pragma unroll
            for (int tm = 0; tm < 2; tm++)
#pragma unroll
                for (int tn = 0; tn < 8; tn++) {
                    asm volatile(
                        "mma.sync.aligned.m16n8k8.row.col.f32.tf32.tf32.f32 "
                        "{%0,%1,%2,%3}, {%4,%5,%6,%7}, {%8,%9}, {%0,%1,%2,%3};\n"
                        : "+f"(acc[tm][tn][0]), "+f"(acc[tm][tn][1]),
                          "+f"(acc[tm][tn][2]), "+f"(acc[tm][tn][3])
                        : "r"(af[tm][0]), "r"(af[tm][1]), "r"(af[tm][2]), "r"(af[tm][3]),
                          "r"(bf[tn][0]), "r"(bf[tn][1]));
                }
        }

        if (has_next) {
            int nb = buf ^ 1;
            *(float4*)&As[nb][a_row][a_col] =
                make_float4(cvt_tf32(ra0.x), cvt_tf32(ra0.y), cvt_tf32(ra0.z), cvt_tf32(ra0.w));
            *(float4*)&As[nb][a_row + 64][a_col] =
                make_float4(cvt_tf32(ra1.x), cvt_tf32(ra1.y), cvt_tf32(ra1.z), cvt_tf32(ra1.w));
            *(float4*)&Bs[nb][b_col][b_r8] =
                make_float4(cvt_tf32(rb[0]), cvt_tf32(rb[1]), cvt_tf32(rb[2]), cvt_tf32(rb[3]));
            *(float4*)&Bs[nb][b_col][b_r8 + 4] =
                make_float4(cvt_tf32(rb[4]), cvt_tf32(rb[5]), cvt_tf32(rb[6]), cvt_tf32(rb[7]));
            __syncthreads();
            buf = nb;
        }
    }

    // ---- epilogue: bias add + store ----
#pragma unroll
    for (int tm = 0; tm < 2; tm++) {
        int row = bm * BM + warp_m * 32 + tm * 16 + gid;
#pragma unroll
        for (int tn = 0; tn < 8; tn++) {
            int col = bn * BN + warp_n * 64 + tn * 8 + 2 * tig;
            float2 bv = *(const float2*)(bz + col);
            float2 o0, o1;
            o0.x = acc[tm][tn][0] + bv.x;
            o0.y = acc[tm][tn][1] + bv.y;
            o1.x = acc[tm][tn][2] + bv.x;
            o1.y = acc[tm][tn][3] + bv.y;
            *(float2*)(Cz + (size_t)row * N + col) = o0;
            *(float2*)(Cz + (size_t)(row + 8) * N + col) = o1;
        }
    }
}

// ------------------------------------------------------------------
// Banded attention: one warp per (b, i_local, h).
// dir=0 (left):  keys j in [max(0,i-9), i]
// dir=1 (right): keys j in [i, min(S2-1, i+9)]
// ------------------------------------------------------------------
__global__ void banded_attn_kernel(const float* __restrict__ Q,
                                   const float* __restrict__ K,
                                   const float* __restrict__ V,
                                   float* __restrict__ O,
                                   int dir) {
    int warp_g = (blockIdx.x * blockDim.x + threadIdx.x) >> 5;
    int lane = threadIdx.x & 31;
    if (warp_g >= B_ * S_ * H_) return;
    int h = warp_g % H_;
    int rem = warp_g / H_;
    int i_local = rem % S_;
    int b = rem / S_;
    int i = i_local + WIDTH_;                 // row in S2 space

    int j0, j1;
    if (dir == 0) { j0 = i - (WIDTH_ + 1); if (j0 < 0) j0 = 0; j1 = i; }
    else          { j0 = i; j1 = i + (WIDTH_ + 1); if (j1 > S2_ - 1) j1 = S2_ - 1; }
    int nj = j1 - j0 + 1;                     // <= 10

    int dcol = h * DK_ + lane * 2;
    const float2 qv = *(const float2*)(Q + ((size_t)(b * S2_ + i)) * D_ + dcol);

    float sc[WIDTH_ + 2];
    for (int t = 0; t < nj; t++) {
        int j = j0 + t;
        float2 kv = *(const float2*)(K + ((size_t)(b * S2_ + j)) * D_ + dcol);
        float p = qv.x * kv.x + qv.y * kv.y;
#pragma unroll
        for (int off = 16; off > 0; off >>= 1)
            p += __shfl_xor_sync(0xffffffffu, p, off);
        sc[t] = p * 0.125f;   // 1/sqrt(64)
    }
    float m = sc[0];
    for (int t = 1; t < nj; t++) m = fmaxf(m, sc[t]);
    float ssum = 0.f;
    for (int t = 0; t < nj; t++) { sc[t] = __expf(sc[t] - m); ssum += sc[t]; }
    float inv = 1.0f / ssum;

    float2 o = make_float2(0.f, 0.f);
    for (int t = 0; t < nj; t++) {
        int j = j0 + t;
        float2 vv = *(const float2*)(V + ((size_t)(b * S2_ + j)) * D_ + dcol);
        float w = sc[t] * inv;
        o.x += w * vv.x;
        o.y += w * vv.y;
    }
    *(float2*)(O + ((size_t)(b * S_ + i_local)) * D_ + dcol) = o;
}

// ------------------------------------------------------------------
// Relative-position add
// ------------------------------------------------------------------
__global__ void rel_add_kernel(float* __restrict__ cur,
                               const float* __restrict__ newin,
                               const float* __restrict__ w,
                               int off) {
    int idx = blockIdx.x * blockDim.x + threadIdx.x;   // over float4
    int total = MROWS_MID * (D_ / 4);
    if (idx >= total) return;
    int d4 = idx % (D_ / 4);
    int row = idx / (D_ / 4);
    int s = row % S_;
    int b = row / S_;

    float4 acc = ((float4*)cur)[(size_t)row * (D_ / 4) + d4];
#pragma unroll
    for (int j = 0; j <= WIDTH_; j++) {
        float wj = w[j];
        float4 v = ((const float4*)newin)[((size_t)(b * S2_ + s + off + j)) * (D_ / 4) + d4];
        acc.x += wj * v.x; acc.y += wj * v.y; acc.z += wj * v.z; acc.w += wj * v.w;
    }
    ((float4*)cur)[(size_t)row * (D_ / 4) + d4] = acc;
}

// ------------------------------------------------------------------
// Highway combine: new = g*cur + (1-g)*relu(nl)
// ------------------------------------------------------------------
__global__ void highway_combine_kernel(const float* __restrict__ proj,
                                       const float* __restrict__ cur,
                                       float* __restrict__ outp,
                                       int out_stride, int col_off) {
    int idx = blockIdx.x * blockDim.x + threadIdx.x;   // over float4
    int total = MROWS_MID * (D_ / 4);
    if (idx >= total) return;
    int d4 = idx % (D_ / 4);
    int row = idx / (D_ / 4);

    float4 nl = ((const float4*)proj)[(size_t)row * (2 * D_ / 4) + d4];
    float4 gp = ((const float4*)proj)[(size_t)row * (2 * D_ / 4) + (D_ / 4) + d4];
    float4 xc = ((const float4*)cur)[(size_t)row * (D_ / 4) + d4];

    float4 o;
    {
        float g = 1.0f / (1.0f + __expf(-gp.x));
        o.x = g * xc.x + (1.0f - g) * fmaxf(nl.x, 0.f);
    }
    {
        float g = 1.0f / (1.0f + __expf(-gp.y));
        o.y = g * xc.y + (1.0f - g) * fmaxf(nl.y, 0.f);
    }
    {
        float g = 1.0f / (1.0f + __expf(-gp.z));
        o.z = g * xc.z + (1.0f - g) * fmaxf(nl.z, 0.f);
    }
    {
        float g = 1.0f / (1.0f + __expf(-gp.w));
        o.w = g * xc.w + (1.0f - g) * fmaxf(nl.w, 0.f);
    }
    *(float4*)(outp + (size_t)row * out_stride + col_off + d4 * 4) = o;
}

// ------------------------------------------------------------------
// Host orchestration
// ------------------------------------------------------------------
extern "C" void kernel_launch(void* const* d_in, const int* in_sizes, int n_in,
                              void* d_out, int out_size) {
    const float* x       = (const float*)d_in[0];
    const float* lattnW  = (const float*)d_in[1];
    const float* lattnB  = (const float*)d_in[2];
    const float* rattnW  = (const float*)d_in[3];
    const float* rattnB  = (const float*)d_in[4];
    const float* lpad    = (const float*)d_in[5];
    const float* rpad    = (const float*)d_in[6];
    const float* leftw   = (const float*)d_in[7];
    const float* rightw  = (const float*)d_in[8];
    const float* lhwW    = (const float*)d_in[9];
    const float* lhwB    = (const float*)d_in[10];
    const float* rhwW    = (const float*)d_in[11];
    const float* rhwB    = (const float*)d_in[12];
    float* out = (float*)d_out;

    float *newin, *qkv, *attn, *cur, *proj;
    cudaGetSymbolAddress((void**)&newin, g_newin);
    cudaGetSymbolAddress((void**)&qkv,   g_qkv);
    cudaGetSymbolAddress((void**)&attn,  g_attn);
    cudaGetSymbolAddress((void**)&cur,   g_cur);
    cudaGetSymbolAddress((void**)&proj,  g_proj);

    // 1. build padded input
    {
        int total = MROWS_FULL * (D_ / 4);
        build_newin_kernel<<<(total + 255) / 256, 256>>>(x, lpad, rpad, newin);
    }

    const float* q = qkv;
    const float* k = qkv + (size_t)MROWS_FULL * D_;
    const float* v = qkv + 2 * (size_t)MROWS_FULL * D_;

    for (int side = 0; side < 2; side++) {
        const float* W   = side ? rattnW : lattnW;
        const float* bb  = side ? rattnB : lattnB;
        const float* hwW = side ? rhwW : lhwW;
        const float* hwB = side ? rhwB : lhwB;
        const float* rw  = side ? rightw : leftw;
        int rel_off = side ? WIDTH_ : 0;

        // QKV projections, fused via grid.z = 3
        {
            dim3 g(D_ / BN, MROWS_FULL / BM, 3);   // 4 x 65 x 3
            tf32_gemm_bias<<<g, 256>>>(newin, W, bb, qkv,
                                       MROWS_FULL, D_, D_,
                                       (long)D_ * D_, D_, (long)MROWS_FULL * D_);
        }

        // banded attention (middle rows only)
        {
            int warps = B_ * S_ * H_;              // 65536
            int threads = 256;
            int blocks = (warps * 32 + threads - 1) / threads;
            banded_attn_kernel<<<blocks, threads>>>(q, k, v, attn, side);
        }

        // output projection -> cur
        {
            dim3 g(D_ / BN, MROWS_MID / BM, 1);    // 4 x 64
            tf32_gemm_bias<<<g, 256>>>(attn, W + 3 * D_ * D_, bb + 3 * D_, cur,
                                       MROWS_MID, D_, D_, 0, 0, 0);
        }

        // add relative-position term
        {
            int total = MROWS_MID * (D_ / 4);
            rel_add_kernel<<<(total + 255) / 256, 256>>>(cur, newin, rw, rel_off);
        }

        // highway layers
        for (int l = 0; l < NHW_; l++) {
            dim3 g(2 * D_ / BN, MROWS_MID / BM, 1);   // 8 x 64
            tf32_gemm_bias<<<g, 256>>>(cur, hwW + (size_t)l * D_ * 2 * D_,
                                       hwB + (size_t)l * 2 * D_, proj,
                                       MROWS_MID, 2 * D_, D_, 0, 0, 0);
            int total = MROWS_MID * (D_ / 4);
            if (l == NHW_ - 1) {
                highway_combine_kernel<<<(total + 255) / 256, 256>>>(
                    proj, cur, out, 2 * D_, side * D_);
            } else {
                highway_combine_kernel<<<(total + 255) / 256, 256>>>(
                    proj, cur, cur, D_, 0);
            }
        }
    }
}